// round 3
// baseline (speedup 1.0000x reference)
#include <cuda_runtime.h>
#include <cuda_fp16.h>
#include <cstdint>

// Problem dims
#define NB 4
#define NT 512
#define NU 128
#define ND 512
#define NV 1024

#define NSUB 128              // N columns per n-iteration
#define NITERS (NV / NSUB)    // 8
#define KC 64                 // K chunk (B tile depth)
#define NCH (ND / KC)         // 8
#define NTHREADS 512

// SMEM layout (dynamic)
#define OFF_SRC  0                      // 512 f32 = 2048B
#define OFF_BIAS 2048                   // 1024 f32 = 4096B
#define OFF_A    8192                   // 128 x 512 f16 = 131072B (row stride 1024B)
#define OFF_B    (8192 + 131072)        // 2 x (128 x 64 f16 = 16384B)
#define BBUF     16384
#define SMEM_TOTAL (OFF_B + 2 * BBUF)   // 172032

// Swizzles: xor bits [4:6] of the k-byte offset with low 3 row bits -> the 8
// rows of each ldmatrix phase hit 8 distinct 16B slots of a 128B span.
#define ASW(row, kbyte) ((uint32_t)((row) * 1024u + ((uint32_t)(kbyte) ^ (((uint32_t)(row) & 7u) << 4))))
#define BSW(n, kbyte)   ((uint32_t)((n) * 128u  + ((uint32_t)(kbyte) ^ (((uint32_t)(n) & 7u) << 4))))

// fp16 copy of W (V x D), written once per launch
static __device__ __half g_Whalf[NV * ND];

__device__ __forceinline__ uint32_t smem_u32(const void* p) {
    uint32_t a;
    asm("{ .reg .u64 t; cvta.to.shared.u64 t, %1; cvt.u32.u64 %0, t; }" : "=r"(a) : "l"(p));
    return a;
}

__device__ __forceinline__ void cp_async16(uint32_t dst, const void* src) {
    asm volatile("cp.async.cg.shared.global [%0], [%1], 16;" :: "r"(dst), "l"(src) : "memory");
}
__device__ __forceinline__ void cp_commit() {
    asm volatile("cp.async.commit_group;" ::: "memory");
}
__device__ __forceinline__ void cp_wait1() {
    asm volatile("cp.async.wait_group 1;" ::: "memory");
}
__device__ __forceinline__ void cp_wait0() {
    asm volatile("cp.async.wait_group 0;" ::: "memory");
}

__device__ __forceinline__ void ldmatrix_x4(uint32_t& r0, uint32_t& r1, uint32_t& r2,
                                            uint32_t& r3, uint32_t addr) {
    asm volatile("ldmatrix.sync.aligned.m8n8.x4.shared.b16 {%0,%1,%2,%3}, [%4];"
                 : "=r"(r0), "=r"(r1), "=r"(r2), "=r"(r3) : "r"(addr));
}

__device__ __forceinline__ void mma_16816(float& c0, float& c1, float& c2, float& c3,
                                          uint32_t a0, uint32_t a1, uint32_t a2, uint32_t a3,
                                          uint32_t b0, uint32_t b1) {
    asm volatile("mma.sync.aligned.m16n8k16.row.col.f32.f16.f16.f32 "
                 "{%0,%1,%2,%3}, {%4,%5,%6,%7}, {%8,%9}, {%0,%1,%2,%3};"
                 : "+f"(c0), "+f"(c1), "+f"(c2), "+f"(c3)
                 : "r"(a0), "r"(a1), "r"(a2), "r"(a3), "r"(b0), "r"(b1));
}

__device__ __forceinline__ float gelu_exact(float x) {
    return 0.5f * x * (1.0f + erff(x * 0.70710678118654752f));
}

// ---------------------------------------------------------------------------
// Kernel 1: convert W (fp32, V x D) to fp16
__global__ void wconv_kernel(const float* __restrict__ W) {
    int i = (blockIdx.x * blockDim.x + threadIdx.x) * 4;  // 512 * 256 * 4 = 524288 = V*D
    float4 v = *reinterpret_cast<const float4*>(W + i);
    __half2 h0 = __floats2half2_rn(v.x, v.y);
    __half2 h1 = __floats2half2_rn(v.z, v.w);
    uint2 o;
    o.x = *reinterpret_cast<uint32_t*>(&h0);
    o.y = *reinterpret_cast<uint32_t*>(&h1);
    *reinterpret_cast<uint2*>(g_Whalf + i) = o;
}

// ---------------------------------------------------------------------------
// Kernel 2: fused gelu + GEMM via mma.sync (HMMA). One CTA per (b,t):
// A tile (128 u-rows x 512 k) gelu'd once into SMEM; loop 8 N-subtiles of
// 128, streaming W-f16 through a double-buffered cp.async ring.
__global__ __launch_bounds__(NTHREADS, 1)
void joiner_kernel(const float* __restrict__ src, const float* __restrict__ tgt,
                   const float* __restrict__ bias, float* __restrict__ out) {
    extern __shared__ char smem[];
    const uint32_t sb = smem_u32(smem);
    const int tid = threadIdx.x;
    const int wid = tid >> 5;
    const int lid = tid & 31;
    const int t = blockIdx.x;
    const int b = blockIdx.y;

    float* src_s = reinterpret_cast<float*>(smem + OFF_SRC);
    float* bias_s = reinterpret_cast<float*>(smem + OFF_BIAS);
    src_s[tid] = src[(size_t)(b * NT + t) * ND + tid];
    bias_s[tid] = bias[tid];
    bias_s[tid + 512] = bias[tid + 512];
    __syncthreads();

    // --- A tile: gelu(src + tgt) -> f16 in swizzled SMEM ---
    {
        const int arow = tid >> 2;                 // u row 0..127
        const int aq = tid & 3;                    // which 128-col quarter
        const float* trow = tgt + (size_t)(b * NU + arow) * ND + aq * 128;
        const float* srow = src_s + aq * 128;
#pragma unroll
        for (int cc = 0; cc < 128; cc += 8) {
            float4 v0 = *reinterpret_cast<const float4*>(trow + cc);
            float4 v1 = *reinterpret_cast<const float4*>(trow + cc + 4);
            float4 s0 = *reinterpret_cast<const float4*>(srow + cc);
            float4 s1 = *reinterpret_cast<const float4*>(srow + cc + 4);
            __half2 h0 = __floats2half2_rn(gelu_exact(v0.x + s0.x), gelu_exact(v0.y + s0.y));
            __half2 h1 = __floats2half2_rn(gelu_exact(v0.z + s0.z), gelu_exact(v0.w + s0.w));
            __half2 h2 = __floats2half2_rn(gelu_exact(v1.x + s1.x), gelu_exact(v1.y + s1.y));
            __half2 h3 = __floats2half2_rn(gelu_exact(v1.z + s1.z), gelu_exact(v1.w + s1.w));
            uint4 pk;
            pk.x = *reinterpret_cast<uint32_t*>(&h0);
            pk.y = *reinterpret_cast<uint32_t*>(&h1);
            pk.z = *reinterpret_cast<uint32_t*>(&h2);
            pk.w = *reinterpret_cast<uint32_t*>(&h3);
            uint32_t kbyte = (uint32_t)(aq * 128 + cc) * 2;
            *reinterpret_cast<uint4*>(smem + OFF_A + ASW(arow, kbyte)) = pk;
        }
    }
    __syncthreads();

    // warp tiling: 4 (m) x 4 (n) warps of 32x32 tiles
    const int wm = wid & 3;
    const int wn = wid >> 2;

    // per-lane ldmatrix row mappings
    const int a_r = (lid & 7) + (((lid >> 3) & 1) << 3);     // 0..15 row within 16
    const int a_kh = (lid >> 4);                              // k-half (0/1) * 8
    const int b_n = (lid & 7) + (((lid >> 4) & 1) << 3);      // 0..15 n within 16
    const int b_kh = ((lid >> 3) & 1);                        // k-half (0/1) * 8

    // B tile loader mapping: 1024 16B chunks, 2 per thread
    const int li0 = tid;          // chunk index pass 0
    const int li1 = tid + 512;    // pass 1

    for (int ni = 0; ni < NITERS; ++ni) {
        const int nbase = ni * NSUB;
        const __half* Wn = g_Whalf + (size_t)nbase * ND;

        float acc[2][4][4];
#pragma unroll
        for (int mt = 0; mt < 2; ++mt)
#pragma unroll
            for (int j = 0; j < 4; ++j)
#pragma unroll
                for (int q = 0; q < 4; ++q) acc[mt][j][q] = 0.0f;

        // preload chunk 0
        {
            const uint32_t Bb = sb + OFF_B;
#pragma unroll
            for (int p = 0; p < 2; ++p) {
                int i = p ? li1 : li0;
                int n = i >> 3, k8 = i & 7;
                cp_async16(Bb + BSW(n, k8 * 16), Wn + (size_t)n * ND + k8 * 8);
            }
            cp_commit();
        }

        for (int c = 0; c < NCH; ++c) {
            if (c + 1 < NCH) {
                const uint32_t Bb = sb + OFF_B + ((c + 1) & 1) * BBUF;
                const __half* Wc = Wn + (c + 1) * KC;
#pragma unroll
                for (int p = 0; p < 2; ++p) {
                    int i = p ? li1 : li0;
                    int n = i >> 3, k8 = i & 7;
                    cp_async16(Bb + BSW(n, k8 * 16), Wc + (size_t)n * ND + k8 * 8);
                }
                cp_commit();
                cp_wait1();
            } else {
                cp_wait0();
            }
            __syncthreads();

            const uint32_t Bbase = sb + OFF_B + (c & 1) * BBUF;
#pragma unroll
            for (int ks = 0; ks < 4; ++ks) {
                const int k0 = c * KC + ks * 16;          // global k of this step
                const uint32_t kb_a = (uint32_t)(k0 + a_kh * 8) * 2;
                // A fragments: m-tiles 0 and 1 (rows wm*32 + {0,16})
                uint32_t a0[4], a1[4];
                {
                    int r = wm * 32 + a_r;
                    ldmatrix_x4(a0[0], a0[1], a0[2], a0[3], sb + OFF_A + ASW(r, kb_a));
                    r += 16;
                    ldmatrix_x4(a1[0], a1[1], a1[2], a1[3], sb + OFF_A + ASW(r, kb_a));
                }
                // B fragments: n16 groups at wn*32 + {0,16}; k within chunk
                const uint32_t kb_b = (uint32_t)(ks * 16 + b_kh * 8) * 2;
                uint32_t bf[8];
                {
                    int n = wn * 32 + b_n;
                    ldmatrix_x4(bf[0], bf[1], bf[2], bf[3], Bbase + BSW(n, kb_b));
                    n += 16;
                    ldmatrix_x4(bf[4], bf[5], bf[6], bf[7], Bbase + BSW(n, kb_b));
                }
#pragma unroll
                for (int mt = 0; mt < 2; ++mt) {
                    uint32_t* a = mt ? a1 : a0;
#pragma unroll
                    for (int j = 0; j < 4; ++j) {
                        mma_16816(acc[mt][j][0], acc[mt][j][1], acc[mt][j][2], acc[mt][j][3],
                                  a[0], a[1], a[2], a[3], bf[2 * j], bf[2 * j + 1]);
                    }
                }
            }
            __syncthreads();
        }

        // --- epilogue: bias + store (each STG covers whole 32B sectors) ---
        const size_t rowbase = (size_t)((b * NT + t) * NU);
#pragma unroll
        for (int mt = 0; mt < 2; ++mt) {
            const int r = wm * 32 + mt * 16 + (lid >> 2);
#pragma unroll
            for (int j = 0; j < 4; ++j) {
                const int col = nbase + wn * 32 + j * 8 + (lid & 3) * 2;
                const float bi0 = bias_s[col], bi1 = bias_s[col + 1];
                float2 o0, o1;
                o0.x = acc[mt][j][0] + bi0;
                o0.y = acc[mt][j][1] + bi1;
                o1.x = acc[mt][j][2] + bi0;
                o1.y = acc[mt][j][3] + bi1;
                *reinterpret_cast<float2*>(out + (rowbase + r) * NV + col) = o0;
                *reinterpret_cast<float2*>(out + (rowbase + r + 8) * NV + col) = o1;
            }
        }
    }
}

// ---------------------------------------------------------------------------
// Kernel 3: length passthrough tail (value-cast int -> float), if present
__global__ void tail_kernel(const int* __restrict__ sl, const int* __restrict__ tl,
                            float* __restrict__ out, int extra) {
    int i = threadIdx.x;
    if (i < 4 && i < extra) out[i] = (float)sl[i];
    if (i >= 4 && i < 8 && i < extra) out[i] = (float)tl[i - 4];
}

// ---------------------------------------------------------------------------
extern "C" void kernel_launch(void* const* d_in, const int* in_sizes, int n_in,
                              void* d_out, int out_size) {
    const float* src  = (const float*)d_in[0];
    const int*   slen = (const int*)d_in[1];
    const float* tgt  = (const float*)d_in[2];
    const int*   tlen = (const int*)d_in[3];
    const float* W    = (const float*)d_in[4];
    const float* bias = (const float*)d_in[5];
    float* out = (float*)d_out;

    cudaFuncSetAttribute(joiner_kernel, cudaFuncAttributeMaxDynamicSharedMemorySize, SMEM_TOTAL);

    wconv_kernel<<<512, 256>>>(W);

    dim3 grid(NT, NB);  // (512, 4) -> 2048 CTAs, one per (b,t)
    joiner_kernel<<<grid, NTHREADS, SMEM_TOTAL>>>(src, tgt, bias, out);

    const long long main_elems = (long long)NB * NT * NU * NV;  // 268435456
    long long extra = (long long)out_size - main_elems;
    if (extra > 0) {
        tail_kernel<<<1, 32>>>(slen, tlen, out + main_elems, (int)extra);
    }
}